// round 14
// baseline (speedup 1.0000x reference)
#include <cuda_runtime.h>
#include <cuda_bf16.h>
#include <cuda_fp16.h>
#include <mma.h>
#include <math.h>
#include <stdint.h>

using namespace nvcuda;

#define BB  512
#define NNt 256
#define DD  128
#define DIi 256
#define NLv 4
#define NSv 16
#define MT  (BB*NNt)

#define LDA1 136       // GEMM1 smem leading dim (K=128 + 8)
#define LDK  72        // GEMM2 smem leading dim (K-chunk 64 + 8)

// ------------------ scratch (device globals; no allocation) ------------------
__device__ float g_X [MT*DD];
__device__ __half g_XZ[MT*2*DIi];        // fp16 in-proj output
__device__ float g_LG[MT];               // logits scratch
__device__ __half g_H [MT*DD];           // LN output, fp16
__device__ __half g_Y [MT*DIi];          // gated ssm output, fp16
__device__ __half g_Wi[NLv*2*DIi*DD];    // W_in  fp16
__device__ __half g_Wo[NLv*DD*DIi];      // W_out fp16
__device__ float g_P [NLv*NNt*NSv];
__device__ float g_CF[NLv*NNt*NSv];

// ------------------ per-layer SSM coefficient tables ------------------
__global__ void prep_kernel(const float* __restrict__ ssm_B,
                            const float* __restrict__ ssm_C,
                            const float* __restrict__ log_dt) {
    int li = blockIdx.x;
    int l  = threadIdx.x;
    float dt = expf(log_dt[li]);
    dt = fminf(fmaxf(dt, 1e-4f), 1.0f);
    for (int n = 0; n < NSv; n++) {
        float A  = -(float)(n + 1);
        float t  = fminf(fmaxf(dt * A, -10.0f), 10.0f);
        float dA = expf(t);
        float dB = (dA - 1.0f) / fminf(A, -1e-4f) * ssm_B[li*NSv + n];
        g_P [(li*NNt + l)*NSv + n] = expf((float)l * t);
        g_CF[(li*NNt + l)*NSv + n] = ssm_C[li*NSv + n] * dB * expf((float)(NNt - 1 - l) * t);
    }
}

// ------------------ fp32 -> fp16 weight convert ------------------
__global__ void wconv_kernel(const float* __restrict__ src,
                             __half* __restrict__ dst, int n) {
    int i = blockIdx.x * 256 + threadIdx.x;
    if (i < n) dst[i] = __float2half_rn(src[i]);
}

// ------------------ initial LayerNorm (+pos) -> X, fp16 H ------------------
__global__ void __launch_bounds__(128) ln_kernel(const float* __restrict__ in,
                                                 const float* __restrict__ pos,
                                                 const float* __restrict__ g,
                                                 const float* __restrict__ b) {
    int lane = threadIdx.x & 31, w = threadIdx.x >> 5;
    long tk = (long)blockIdx.x * 4 + w;
    float4 v = *(const float4*)(in + tk*DD + lane*4);
    int n = (int)(tk % NNt);
    float4 p = *(const float4*)(pos + (long)n*DD + lane*4);
    v.x += p.x; v.y += p.y; v.z += p.z; v.w += p.w;
    *(float4*)(g_X + tk*DD + lane*4) = v;
    float s = v.x + v.y + v.z + v.w;
#pragma unroll
    for (int o = 16; o > 0; o >>= 1) s += __shfl_xor_sync(0xffffffffu, s, o);
    float m = s * (1.0f/DD);
    float d0 = v.x-m, d1 = v.y-m, d2 = v.z-m, d3 = v.w-m;
    float q = d0*d0 + d1*d1 + d2*d2 + d3*d3;
#pragma unroll
    for (int o = 16; o > 0; o >>= 1) q += __shfl_xor_sync(0xffffffffu, q, o);
    float r = rsqrtf(q * (1.0f/DD) + 1e-5f);
    float4 gg = *(const float4*)(g + lane*4);
    float4 bb = *(const float4*)(b + lane*4);
    union { __half2 h[2]; uint2 u2; } pk;
    pk.h[0] = __floats2half2_rn(d0*r*gg.x + bb.x, d1*r*gg.y + bb.y);
    pk.h[1] = __floats2half2_rn(d2*r*gg.z + bb.z, d3*r*gg.w + bb.w);
    *(uint2*)(g_H + tk*DD + lane*4) = pk.u2;
}

// ------------------ GEMM1: XZ = H @ W_in^T, fp16, K=128, N=512; 3 CTAs/SM -----
// smem: A(34816) B(17408) stage(64x68 fp32 = 17408) = 69632
#define G1_AB 34816
#define G1_BB 17408
__global__ void __launch_bounds__(256, 3)
gemm_in_kernel(const __half* __restrict__ A, const __half* __restrict__ B,
               __half* __restrict__ C) {
    extern __shared__ char sm[];
    char* sA = sm;
    char* sB = sm + G1_AB;
    float* stage = (float*)(sm + G1_AB + G1_BB);     // 64 x 68 fp32

    int t = threadIdx.x;
    int warp = t >> 5;
    int wm = warp & 3, wn = warp >> 2;               // warp tile 32 x 32
    long m0 = (long)blockIdx.x * 128;

    // load A resident: 128 rows x 16 chunks of 16B
#pragma unroll
    for (int u = 0; u < 8; u++) {
        int id = t + u*256;
        int r = id >> 4, c = id & 15;
        *(uint4*)(sA + r*(LDA1*2) + c*16) = *(const uint4*)(A + (m0 + r)*(long)DD + c*8);
    }

    for (int nb = 0; nb < 8; nb++) {
        long n0 = (long)nb * 64;
        __syncthreads();
#pragma unroll
        for (int u = 0; u < 4; u++) {
            int id = t + u*256;                      // 1024 chunks
            int r = id >> 4, c = id & 15;
            *(uint4*)(sB + r*(LDA1*2) + c*16) = *(const uint4*)(B + (n0 + r)*(long)DD + c*8);
        }
        __syncthreads();

        wmma::fragment<wmma::accumulator, 16, 16, 16, float> acc[2][2];
#pragma unroll
        for (int i = 0; i < 2; i++)
#pragma unroll
            for (int j = 0; j < 2; j++) wmma::fill_fragment(acc[i][j], 0.0f);

#pragma unroll
        for (int ks = 0; ks < 8; ks++) {
            wmma::fragment<wmma::matrix_a, 16, 16, 16, __half, wmma::row_major> af[2];
            wmma::fragment<wmma::matrix_b, 16, 16, 16, __half, wmma::col_major> bf[2];
#pragma unroll
            for (int i = 0; i < 2; i++)
                wmma::load_matrix_sync(af[i], (const __half*)sA + (wm*32 + i*16)*LDA1 + ks*16, LDA1);
#pragma unroll
            for (int j = 0; j < 2; j++)
                wmma::load_matrix_sync(bf[j], (const __half*)sB + (wn*32 + j*16)*LDA1 + ks*16, LDA1);
#pragma unroll
            for (int i = 0; i < 2; i++)
#pragma unroll
                for (int j = 0; j < 2; j++)
                    wmma::mma_sync(acc[i][j], af[i], bf[j], acc[i][j]);
        }

        // epilogue: two 64-row passes through the half-size stage
#pragma unroll
        for (int p = 0; p < 2; p++) {
            if ((wm >> 1) == p) {
#pragma unroll
                for (int i = 0; i < 2; i++)
#pragma unroll
                    for (int j = 0; j < 2; j++)
                        wmma::store_matrix_sync(
                            stage + ((wm & 1)*32 + i*16)*68 + wn*32 + j*16,
                            acc[i][j], 68, wmma::mem_row_major);
            }
            __syncthreads();
#pragma unroll
            for (int u = 0; u < 4; u++) {
                int id = t + u*256;                  // 1024 groups of 4 cols
                int r = id >> 4, q = id & 15;        // r 0..63, q 0..15
                float4 v;
                v.x = stage[r*68 + q*4 + 0]; v.y = stage[r*68 + q*4 + 1];
                v.z = stage[r*68 + q*4 + 2]; v.w = stage[r*68 + q*4 + 3];
                union { __half2 h[2]; uint2 u2; } pk;
                pk.h[0] = __floats2half2_rn(v.x, v.y);
                pk.h[1] = __floats2half2_rn(v.z, v.w);
                *(uint2*)(C + (m0 + p*64 + r)*(long)(2*DIi) + n0 + q*4) = pk.u2;
            }
            __syncthreads();
        }
    }
}

// ------------------ GEMM2: X += rs*(Y @ W_out^T), fp16, K=256; fused next-LN --
// smem: A(18432) B(18432) stage(64x132 fp32 = 33792) = 70656; 3 CTAs/SM
#define G2_MB 18432
__global__ void __launch_bounds__(256, 3)
gemm_out_kernel(const __half* __restrict__ A, const __half* __restrict__ B,
                float* __restrict__ X, const float* __restrict__ rs,
                const float* __restrict__ lng, const float* __restrict__ lnb,
                __half* __restrict__ H, int doLN) {
    extern __shared__ char sm[];
    char* sA = sm;
    char* sB = sm + G2_MB;
    float* stage = (float*)(sm + 2*G2_MB);           // 64 x 132 fp32

    int t = threadIdx.x;
    int warp = t >> 5, lane = t & 31;
    int wm = warp >> 1, wn = warp & 1;               // warp tile 32 x 64
    long m0 = (long)blockIdx.x * 128;

    wmma::fragment<wmma::accumulator, 16, 16, 16, float> acc[2][4];
#pragma unroll
    for (int i = 0; i < 2; i++)
#pragma unroll
        for (int j = 0; j < 4; j++) wmma::fill_fragment(acc[i][j], 0.0f);

    for (int kh = 0; kh < 4; kh++) {
        __syncthreads();
        {
            const __half* srcA = A + m0*(long)DIi + kh*64;
            const __half* srcB = B + kh*64;
#pragma unroll
            for (int u = 0; u < 4; u++) {
                int id = t + u*256;                  // 1024 chunks per matrix; 8/row
                int r = id >> 3, c = id & 7;
                *(uint4*)(sA + r*(LDK*2) + c*16) = *(const uint4*)(srcA + r*(long)DIi + c*8);
                *(uint4*)(sB + r*(LDK*2) + c*16) = *(const uint4*)(srcB + r*(long)DIi + c*8);
            }
        }
        __syncthreads();

#pragma unroll
        for (int ks = 0; ks < 4; ks++) {
            wmma::fragment<wmma::matrix_a, 16, 16, 16, __half, wmma::row_major> af[2];
#pragma unroll
            for (int i = 0; i < 2; i++)
                wmma::load_matrix_sync(af[i], (const __half*)sA + (wm*32 + i*16)*LDK + ks*16, LDK);
#pragma unroll
            for (int j = 0; j < 4; j++) {
                wmma::fragment<wmma::matrix_b, 16, 16, 16, __half, wmma::col_major> bf;
                wmma::load_matrix_sync(bf, (const __half*)sB + (wn*64 + j*16)*LDK + ks*16, LDK);
#pragma unroll
                for (int i = 0; i < 2; i++)
                    wmma::mma_sync(acc[i][j], af[i], bf, acc[i][j]);
            }
        }
    }

    float sc = fminf(fmaxf(rs[0], 0.0f), 1.5f);
    float4 gg, bb4;
    if (doLN) {
        gg  = *(const float4*)(lng + lane*4);
        bb4 = *(const float4*)(lnb + lane*4);
    }

    // epilogue: two 64-row passes through the half-size stage
#pragma unroll
    for (int p = 0; p < 2; p++) {
        __syncthreads();
        if ((wm >> 1) == p) {
#pragma unroll
            for (int i = 0; i < 2; i++)
#pragma unroll
                for (int j = 0; j < 4; j++)
                    wmma::store_matrix_sync(
                        stage + ((wm & 1)*32 + i*16)*132 + wn*64 + j*16,
                        acc[i][j], 132, wmma::mem_row_major);
        }
        __syncthreads();
        // each warp handles 8 rows of this 64-row half
#pragma unroll
        for (int rr = 0; rr < 8; rr++) {
            int lr = warp*8 + rr;                    // 0..63
            long m = m0 + p*64 + lr;
            float4 a4 = *(const float4*)&stage[lr*132 + lane*4];
            float4 r4 = *(const float4*)(X + m*DD + lane*4);
            float4 v;
            v.x = r4.x + sc*a4.x; v.y = r4.y + sc*a4.y;
            v.z = r4.z + sc*a4.z; v.w = r4.w + sc*a4.w;
            *(float4*)(X + m*DD + lane*4) = v;
            if (doLN) {
                float s = v.x + v.y + v.z + v.w;
#pragma unroll
                for (int o = 16; o > 0; o >>= 1) s += __shfl_xor_sync(0xffffffffu, s, o);
                float mm = s * (1.0f/DD);
                float d0 = v.x-mm, d1 = v.y-mm, d2 = v.z-mm, d3 = v.w-mm;
                float q = d0*d0 + d1*d1 + d2*d2 + d3*d3;
#pragma unroll
                for (int o = 16; o > 0; o >>= 1) q += __shfl_xor_sync(0xffffffffu, q, o);
                float r = rsqrtf(q * (1.0f/DD) + 1e-5f);
                union { __half2 h[2]; uint2 u2; } pk;
                pk.h[0] = __floats2half2_rn(d0*r*gg.x + bb4.x, d1*r*gg.y + bb4.y);
                pk.h[1] = __floats2half2_rn(d2*r*gg.z + bb4.z, d3*r*gg.w + bb4.w);
                *(uint2*)(H + m*DD + lane*4) = pk.u2;
            }
        }
    }
}

// ------------------ fused conv(k=4) + S4D recurrence + sigmoid gate ------------
__global__ void __launch_bounds__(256) s4d_kernel(const float* __restrict__ conv_w,
                                                  const float* __restrict__ conv_b,
                                                  const float* __restrict__ ssm_D,
                                                  int li) {
    __shared__ float sP [NNt*NSv];
    __shared__ float sCF[NNt*NSv];
    int c = threadIdx.x;
    int b = blockIdx.x;
    for (int i = c; i < NNt*NSv; i += 256) {
        sP [i] = g_P [li*NNt*NSv + i];
        sCF[i] = g_CF[li*NNt*NSv + i];
    }
    float w0 = conv_w[c*4+0], w1 = conv_w[c*4+1], w2 = conv_w[c*4+2], w3 = conv_w[c*4+3];
    float cb = conv_b[c];
    float Dp = ssm_D[0];
    __syncthreads();

    float S[NSv];
#pragma unroll
    for (int i = 0; i < NSv; i++) S[i] = 0.0f;
    float x0 = 0.f, x1 = 0.f, x2 = 0.f, x3 = 0.f;

    const __half* xzb = g_XZ + (long)b*NNt*(2*DIi);
    __half* yb = g_Y + (long)b*NNt*DIi;

#pragma unroll 2
    for (int l = 0; l < NNt; l++) {
        float xp = __half2float(xzb[l*(2*DIi) + c]);
        float zz = __half2float(xzb[l*(2*DIi) + DIi + c]);
        x0 = x1; x1 = x2; x2 = x3; x3 = xp;
        float xc = fmaf(w0, x0, fmaf(w1, x1, fmaf(w2, x2, fmaf(w3, x3, cb))));

        const float4* p4 = (const float4*)&sP [l*NSv];
        const float4* f4 = (const float4*)&sCF[l*NSv];
        float ys0 = Dp * xc, ys1 = 0.f, ys2 = 0.f, ys3 = 0.f;
#pragma unroll
        for (int q = 0; q < 4; q++) {
            float4 p = p4[q], f = f4[q];
            S[q*4+0] = fmaf(p.x, xc, S[q*4+0]); ys0 = fmaf(f.x, S[q*4+0], ys0);
            S[q*4+1] = fmaf(p.y, xc, S[q*4+1]); ys1 = fmaf(f.y, S[q*4+1], ys1);
            S[q*4+2] = fmaf(p.z, xc, S[q*4+2]); ys2 = fmaf(f.z, S[q*4+2], ys2);
            S[q*4+3] = fmaf(p.w, xc, S[q*4+3]); ys3 = fmaf(f.w, S[q*4+3], ys3);
        }
        float ys = (ys0 + ys1) + (ys2 + ys3);
        float e  = __expf(-zz);
        yb[l*DIi + c] = __float2half_rn(ys / (1.0f + e));
    }
}

// ------------------ final LN + normalize + importance MLP -> logits ------------
__global__ void __launch_bounds__(256) ftoken_kernel(const float* __restrict__ fin_g,
                                                     const float* __restrict__ fin_b,
                                                     const float* __restrict__ W1,
                                                     const float* __restrict__ b1,
                                                     const float* __restrict__ W2,
                                                     const float* __restrict__ b2,
                                                     float* __restrict__ out_tokens,
                                                     float* __restrict__ out_logits) {
    __shared__ float4 sW1[32*64];
    __shared__ float  sW2[64], sb1[64];
    __shared__ float  stn[8][132];
    int t = threadIdx.x;
    for (int f = t; f < 2048; f += 256) {
        int j = f >> 5, k4 = f & 31;
        sW1[k4*64 + j] = ((const float4*)W1)[f];
    }
    if (t < 64) { sW2[t] = W2[t]; sb1[t] = b1[t]; }
    __syncthreads();

    int lane = t & 31, w = t >> 5;
    long tk = (long)blockIdx.x * 8 + w;
    float4 v = *(const float4*)(g_X + tk*DD + lane*4);
    float s = v.x + v.y + v.z + v.w;
#pragma unroll
    for (int o = 16; o > 0; o >>= 1) s += __shfl_xor_sync(0xffffffffu, s, o);
    float m = s * (1.0f/DD);
    float d0 = v.x-m, d1 = v.y-m, d2 = v.z-m, d3 = v.w-m;
    float q = d0*d0 + d1*d1 + d2*d2 + d3*d3;
#pragma unroll
    for (int o = 16; o > 0; o >>= 1) q += __shfl_xor_sync(0xffffffffu, q, o);
    float r = rsqrtf(q * (1.0f/DD) + 1e-5f);
    float4 gg = *(const float4*)(fin_g + lane*4);
    float4 bb = *(const float4*)(fin_b + lane*4);
    float4 tok;
    tok.x = d0*r*gg.x + bb.x; tok.y = d1*r*gg.y + bb.y;
    tok.z = d2*r*gg.z + bb.z; tok.w = d3*r*gg.w + bb.w;
    *(float4*)(out_tokens + tk*DD + lane*4) = tok;

    float ss = tok.x*tok.x + tok.y*tok.y + tok.z*tok.z + tok.w*tok.w;
#pragma unroll
    for (int o = 16; o > 0; o >>= 1) ss += __shfl_xor_sync(0xffffffffu, ss, o);
    float rn = 1.0f / fmaxf(sqrtf(ss), 1e-6f);
    float4 tn4; tn4.x = tok.x*rn; tn4.y = tok.y*rn; tn4.z = tok.z*rn; tn4.w = tok.w*rn;
    *(float4*)&stn[w][lane*4] = tn4;
    __syncwarp();

    float h0 = sb1[lane], h1 = sb1[lane + 32];
#pragma unroll 8
    for (int k4 = 0; k4 < 32; k4++) {
        float4 tt = *(const float4*)&stn[w][k4*4];
        float4 wa = sW1[k4*64 + lane];
        float4 wb = sW1[k4*64 + lane + 32];
        h0 += tt.x*wa.x + tt.y*wa.y + tt.z*wa.z + tt.w*wa.w;
        h1 += tt.x*wb.x + tt.y*wb.y + tt.z*wb.z + tt.w*wb.w;
    }
    h0 = 0.5f*h0*(1.0f + erff(h0*0.70710678118654752f));
    h1 = 0.5f*h1*(1.0f + erff(h1*0.70710678118654752f));
    float gl = h0*sW2[lane] + h1*sW2[lane + 32];
#pragma unroll
    for (int o = 16; o > 0; o >>= 1) gl += __shfl_xor_sync(0xffffffffu, gl, o);
    if (lane == 0) out_logits[tk] = gl + b2[0];
}

// ------------------ softmax over N + weighted token pool -> feats --------------
__global__ void __launch_bounds__(256) fbatch_kernel(const float* __restrict__ logits,
                                                     const float* __restrict__ tokens,
                                                     float* __restrict__ out_w,
                                                     float* __restrict__ out_feats) {
    __shared__ float sw[NNt];
    __shared__ float red[8];
    int b = blockIdx.x, t = threadIdx.x, lane = t & 31, w = t >> 5;
    float lg = logits[(long)b*NNt + t];
    float mx = lg;
#pragma unroll
    for (int o = 16; o > 0; o >>= 1) mx = fmaxf(mx, __shfl_xor_sync(0xffffffffu, mx, o));
    if (lane == 0) red[w] = mx;
    __syncthreads();
    float bm = red[0];
#pragma unroll
    for (int i = 1; i < 8; i++) bm = fmaxf(bm, red[i]);
    float e = expf(lg - bm);
    float se = e;
#pragma unroll
    for (int o = 16; o > 0; o >>= 1) se += __shfl_xor_sync(0xffffffffu, se, o);
    __syncthreads();
    if (lane == 0) red[w] = se;
    __syncthreads();
    float tot = 0.f;
#pragma unroll
    for (int i = 0; i < 8; i++) tot += red[i];
    float wv = e / tot;
    out_w[(long)b*NNt + t] = wv;
    sw[t] = wv;
    __syncthreads();
    if (t < DD) {
        float acc = 0.f;
        for (int n = 0; n < NNt; n++)
            acc += sw[n] * tokens[((long)b*NNt + n)*DD + t];
        out_feats[b*DD + t] = acc;
    }
}

// ------------------ three linear heads -----------------------------------------
__global__ void __launch_bounds__(192) heads_kernel(const float* __restrict__ feats,
        const float* __restrict__ texW, const float* __restrict__ texb,
        const float* __restrict__ edgeW, const float* __restrict__ edgeb,
        const float* __restrict__ strW, const float* __restrict__ strb,
        float* __restrict__ o_tex, float* __restrict__ o_edge, float* __restrict__ o_str) {
    __shared__ float sf[DD];
    int b = blockIdx.x, t = threadIdx.x;
    if (t < DD) sf[t] = feats[b*DD + t];
    __syncthreads();
    int head = t / 64, j = t % 64;
    const float* W  = (head == 0) ? texW : (head == 1) ? edgeW : strW;
    const float* bi = (head == 0) ? texb : (head == 1) ? edgeb : strb;
    float acc = bi[j];
#pragma unroll 4
    for (int k = 0; k < DD; k++) acc += sf[k] * W[j*DD + k];
    float* o = (head == 0) ? o_tex : (head == 1) ? o_edge : o_str;
    o[b*64 + j] = acc;
}

// ------------------ launch ------------------------------------------------------
extern "C" void kernel_launch(void* const* d_in, const int* in_sizes, int n_in,
                              void* d_out, int out_size) {
    const float* tokens_in = (const float*)d_in[0];
    const float* pos       = (const float*)d_in[1];
    const float* ln_g      = (const float*)d_in[2];
    const float* ln_b      = (const float*)d_in[3];
    const float* W_in      = (const float*)d_in[4];
    const float* conv_w    = (const float*)d_in[5];
    const float* conv_b    = (const float*)d_in[6];
    const float* ssm_B     = (const float*)d_in[7];
    const float* ssm_C     = (const float*)d_in[8];
    const float* log_dt    = (const float*)d_in[9];
    const float* ssm_D     = (const float*)d_in[10];
    const float* W_out     = (const float*)d_in[11];
    const float* res_scale = (const float*)d_in[12];
    const float* fin_g     = (const float*)d_in[13];
    const float* fin_b     = (const float*)d_in[14];
    const float* W1        = (const float*)d_in[15];
    const float* b1        = (const float*)d_in[16];
    const float* W2        = (const float*)d_in[17];
    const float* b2        = (const float*)d_in[18];
    const float* texW      = (const float*)d_in[19];
    const float* texb      = (const float*)d_in[20];
    const float* edgeW     = (const float*)d_in[21];
    const float* edgeb     = (const float*)d_in[22];
    const float* strW      = (const float*)d_in[23];
    const float* strb      = (const float*)d_in[24];

    float *pX, *pLG;
    __half *pXZ, *pH, *pY, *pWi, *pWo;
    cudaGetSymbolAddress((void**)&pX,  g_X);
    cudaGetSymbolAddress((void**)&pXZ, g_XZ);
    cudaGetSymbolAddress((void**)&pLG, g_LG);
    cudaGetSymbolAddress((void**)&pH,  g_H);
    cudaGetSymbolAddress((void**)&pY,  g_Y);
    cudaGetSymbolAddress((void**)&pWi, g_Wi);
    cudaGetSymbolAddress((void**)&pWo, g_Wo);

    const int SMEM1 = G1_AB + G1_BB + 17408;   // 69632  -> 3 CTAs/SM
    const int SMEM2 = 2*G2_MB + 33792;         // 70656  -> 3 CTAs/SM
    cudaFuncSetAttribute(gemm_in_kernel,
                         cudaFuncAttributeMaxDynamicSharedMemorySize, SMEM1);
    cudaFuncSetAttribute(gemm_out_kernel,
                         cudaFuncAttributeMaxDynamicSharedMemorySize, SMEM2);

    float* out     = (float*)d_out;
    float* o_feats = out;
    float* o_tex   = o_feats + (long)BB*DD;
    float* o_edge  = o_tex   + (long)BB*64;
    float* o_str   = o_edge  + (long)BB*64;
    float* o_tok   = o_str   + (long)BB*64;
    float* o_w     = o_tok   + (long)BB*NNt*DD;

    const long M = (long)MT;

    prep_kernel<<<NLv, NNt>>>(ssm_B, ssm_C, log_dt);
    wconv_kernel<<<(NLv*2*DIi*DD + 255)/256, 256>>>(W_in,  pWi, NLv*2*DIi*DD);
    wconv_kernel<<<(NLv*DD*DIi   + 255)/256, 256>>>(W_out, pWo, NLv*DD*DIi);
    ln_kernel<<<(unsigned)(M/4), 128>>>(tokens_in, pos, ln_g, ln_b);
    for (int li = 0; li < NLv; li++) {
        gemm_in_kernel<<<(unsigned)(M/128), 256, SMEM1>>>(
            pH, pWi + (long)li*2*DIi*DD, pXZ);
        s4d_kernel<<<BB, DIi>>>(conv_w + li*DIi*4, conv_b + li*DIi, ssm_D + li, li);
        int doLN = (li < NLv - 1) ? 1 : 0;
        gemm_out_kernel<<<(unsigned)(M/128), 256, SMEM2>>>(
            pY, pWo + (long)li*DD*DIi,
            pX, res_scale + li,
            ln_g + (li+1 < NLv ? (li+1)*DD : 0), ln_b + (li+1 < NLv ? (li+1)*DD : 0),
            pH, doLN);
    }
    ftoken_kernel<<<(unsigned)(M/8), 256>>>(fin_g, fin_b, W1, b1, W2, b2, o_tok, pLG);
    fbatch_kernel<<<BB, NNt>>>(pLG, o_tok, o_w, o_feats);
    heads_kernel<<<BB, 192>>>(o_feats, texW, texb, edgeW, edgeb, strW, strb,
                              o_tex, o_edge, o_str);
}

// round 16
// speedup vs baseline: 1.1118x; 1.1118x over previous
#include <cuda_runtime.h>
#include <cuda_bf16.h>
#include <cuda_fp16.h>
#include <mma.h>
#include <math.h>
#include <stdint.h>

using namespace nvcuda;

#define BB  512
#define NNt 256
#define DD  128
#define DIi 256
#define NLv 4
#define NSv 16
#define MT  (BB*NNt)

#define LDA1 136       // smem leading dim for K=128 tiles (128 + 8)
#define LDK  72        // GEMM2 smem leading dim (K-chunk 64 + 8)

// ------------------ scratch (device globals; no allocation) ------------------
__device__ float g_X [MT*DD];
__device__ __half g_XZ[MT*2*DIi];        // fp16 in-proj output
__device__ float g_LG[MT];               // logits scratch
__device__ __half g_H [MT*DD];           // LN output (layer 0 only), fp16
__device__ __half g_Y [MT*DIi];          // gated ssm output, fp16
__device__ __half g_Wi[NLv*2*DIi*DD];    // W_in  fp16
__device__ __half g_Wo[NLv*DD*DIi];      // W_out fp16
__device__ float g_P [NLv*NNt*NSv];
__device__ float g_CF[NLv*NNt*NSv];

// ------------------ per-layer SSM coefficient tables ------------------
__global__ void prep_kernel(const float* __restrict__ ssm_B,
                            const float* __restrict__ ssm_C,
                            const float* __restrict__ log_dt) {
    int li = blockIdx.x;
    int l  = threadIdx.x;
    float dt = expf(log_dt[li]);
    dt = fminf(fmaxf(dt, 1e-4f), 1.0f);
    for (int n = 0; n < NSv; n++) {
        float A  = -(float)(n + 1);
        float t  = fminf(fmaxf(dt * A, -10.0f), 10.0f);
        float dA = expf(t);
        float dB = (dA - 1.0f) / fminf(A, -1e-4f) * ssm_B[li*NSv + n];
        g_P [(li*NNt + l)*NSv + n] = expf((float)l * t);
        g_CF[(li*NNt + l)*NSv + n] = ssm_C[li*NSv + n] * dB * expf((float)(NNt - 1 - l) * t);
    }
}

// ------------------ fp32 -> fp16 weight convert ------------------
__global__ void wconv_kernel(const float* __restrict__ src,
                             __half* __restrict__ dst, int n) {
    int i = blockIdx.x * 256 + threadIdx.x;
    if (i < n) dst[i] = __float2half_rn(src[i]);
}

// ------------------ initial LayerNorm (+pos) -> X, fp16 H ------------------
__global__ void __launch_bounds__(128) ln_kernel(const float* __restrict__ in,
                                                 const float* __restrict__ pos,
                                                 const float* __restrict__ g,
                                                 const float* __restrict__ b) {
    int lane = threadIdx.x & 31, w = threadIdx.x >> 5;
    long tk = (long)blockIdx.x * 4 + w;
    float4 v = *(const float4*)(in + tk*DD + lane*4);
    int n = (int)(tk % NNt);
    float4 p = *(const float4*)(pos + (long)n*DD + lane*4);
    v.x += p.x; v.y += p.y; v.z += p.z; v.w += p.w;
    *(float4*)(g_X + tk*DD + lane*4) = v;
    float s = v.x + v.y + v.z + v.w;
#pragma unroll
    for (int o = 16; o > 0; o >>= 1) s += __shfl_xor_sync(0xffffffffu, s, o);
    float m = s * (1.0f/DD);
    float d0 = v.x-m, d1 = v.y-m, d2 = v.z-m, d3 = v.w-m;
    float q = d0*d0 + d1*d1 + d2*d2 + d3*d3;
#pragma unroll
    for (int o = 16; o > 0; o >>= 1) q += __shfl_xor_sync(0xffffffffu, q, o);
    float r = rsqrtf(q * (1.0f/DD) + 1e-5f);
    float4 gg = *(const float4*)(g + lane*4);
    float4 bb = *(const float4*)(b + lane*4);
    union { __half2 h[2]; uint2 u2; } pk;
    pk.h[0] = __floats2half2_rn(d0*r*gg.x + bb.x, d1*r*gg.y + bb.y);
    pk.h[1] = __floats2half2_rn(d2*r*gg.z + bb.z, d3*r*gg.w + bb.w);
    *(uint2*)(g_H + tk*DD + lane*4) = pk.u2;
}

// ------------------ GEMM1 (layer 0 only): XZ = H @ W_in^T; 2 CTAs/SM ----------
// smem: A(34816) B(17408) stage(34816) = 87040
#define G1_AB 34816
#define G1_BB 17408
__global__ void __launch_bounds__(256, 2)
gemm_in_kernel(const __half* __restrict__ A, const __half* __restrict__ B,
               __half* __restrict__ C) {
    extern __shared__ char sm[];
    char* sA = sm;
    char* sB = sm + G1_AB;
    float* stage = (float*)(sm + G1_AB + G1_BB);     // 128 x 68 fp32

    int t = threadIdx.x;
    int warp = t >> 5;
    int wm = warp & 3, wn = warp >> 2;               // warp tile 32 x 32
    long m0 = (long)blockIdx.x * 128;

#pragma unroll
    for (int u = 0; u < 8; u++) {
        int id = t + u*256;
        int r = id >> 4, c = id & 15;
        *(uint4*)(sA + r*(LDA1*2) + c*16) = *(const uint4*)(A + (m0 + r)*(long)DD + c*8);
    }

    for (int nb = 0; nb < 8; nb++) {
        long n0 = (long)nb * 64;
        __syncthreads();
#pragma unroll
        for (int u = 0; u < 4; u++) {
            int id = t + u*256;
            int r = id >> 4, c = id & 15;
            *(uint4*)(sB + r*(LDA1*2) + c*16) = *(const uint4*)(B + (n0 + r)*(long)DD + c*8);
        }
        __syncthreads();

        wmma::fragment<wmma::accumulator, 16, 16, 16, float> acc[2][2];
#pragma unroll
        for (int i = 0; i < 2; i++)
#pragma unroll
            for (int j = 0; j < 2; j++) wmma::fill_fragment(acc[i][j], 0.0f);

#pragma unroll
        for (int ks = 0; ks < 8; ks++) {
            wmma::fragment<wmma::matrix_a, 16, 16, 16, __half, wmma::row_major> af[2];
            wmma::fragment<wmma::matrix_b, 16, 16, 16, __half, wmma::col_major> bf[2];
#pragma unroll
            for (int i = 0; i < 2; i++)
                wmma::load_matrix_sync(af[i], (const __half*)sA + (wm*32 + i*16)*LDA1 + ks*16, LDA1);
#pragma unroll
            for (int j = 0; j < 2; j++)
                wmma::load_matrix_sync(bf[j], (const __half*)sB + (wn*32 + j*16)*LDA1 + ks*16, LDA1);
#pragma unroll
            for (int i = 0; i < 2; i++)
#pragma unroll
                for (int j = 0; j < 2; j++)
                    wmma::mma_sync(acc[i][j], af[i], bf[j], acc[i][j]);
        }
#pragma unroll
        for (int i = 0; i < 2; i++)
#pragma unroll
            for (int j = 0; j < 2; j++)
                wmma::store_matrix_sync(stage + (wm*32 + i*16)*68 + wn*32 + j*16,
                                        acc[i][j], 68, wmma::mem_row_major);
        __syncthreads();
#pragma unroll
        for (int u = 0; u < 8; u++) {
            int id = t + u*256;
            int r = id >> 4, q = id & 15;
            float4 v;
            v.x = stage[r*68 + q*4 + 0]; v.y = stage[r*68 + q*4 + 1];
            v.z = stage[r*68 + q*4 + 2]; v.w = stage[r*68 + q*4 + 3];
            union { __half2 h[2]; uint2 u2; } pk;
            pk.h[0] = __floats2half2_rn(v.x, v.y);
            pk.h[1] = __floats2half2_rn(v.z, v.w);
            *(uint2*)(C + (m0 + r)*(long)(2*DIi) + n0 + q*4) = pk.u2;
        }
    }
}

// ------- GEMM2 fused: X += rs*(Y @ Wo^T); [LN -> H smem -> XZ_next] ----------
// smem: sA(18432) sB(18432) | big(67584): phase1 stage / phase2 sW+stage1
// total 104448 -> 2 CTAs/SM. sH (34816) overlays sA+sB after phase 1.
#define G2_MB 18432
__global__ void __launch_bounds__(256, 2)
gemm_out_kernel(const __half* __restrict__ A, const __half* __restrict__ B,
                float* __restrict__ X, const float* __restrict__ rs,
                const float* __restrict__ lng, const float* __restrict__ lnb,
                const __half* __restrict__ Wi_next, __half* __restrict__ XZ,
                int doNext) {
    extern __shared__ char sm[];
    char* sA = sm;
    char* sB = sm + G2_MB;
    char* sH = sm;                                   // overlays sA/sB after phase 1
    float* stage  = (float*)(sm + 2*G2_MB);          // 128 x 132 fp32 (phase 1)
    char*  sW     = sm + 2*G2_MB;                    // 64 x LDA1 fp16 (phase 2)
    float* stage1 = (float*)(sm + 2*G2_MB + 17408);  // 128 x 68 fp32 (phase 2)

    int t = threadIdx.x;
    int warp = t >> 5, lane = t & 31;
    int wm = warp >> 1, wn = warp & 1;               // phase-1 warp tile 32 x 64
    long m0 = (long)blockIdx.x * 128;

    // ---------------- phase 1: X += rs * (Y @ Wo^T) ----------------
    wmma::fragment<wmma::accumulator, 16, 16, 16, float> acc[2][4];
#pragma unroll
    for (int i = 0; i < 2; i++)
#pragma unroll
        for (int j = 0; j < 4; j++) wmma::fill_fragment(acc[i][j], 0.0f);

    for (int kh = 0; kh < 4; kh++) {
        __syncthreads();
        {
            const __half* srcA = A + m0*(long)DIi + kh*64;
            const __half* srcB = B + kh*64;
#pragma unroll
            for (int u = 0; u < 4; u++) {
                int id = t + u*256;
                int r = id >> 3, c = id & 7;
                *(uint4*)(sA + r*(LDK*2) + c*16) = *(const uint4*)(srcA + r*(long)DIi + c*8);
                *(uint4*)(sB + r*(LDK*2) + c*16) = *(const uint4*)(srcB + r*(long)DIi + c*8);
            }
        }
        __syncthreads();

#pragma unroll
        for (int ks = 0; ks < 4; ks++) {
            wmma::fragment<wmma::matrix_a, 16, 16, 16, __half, wmma::row_major> af[2];
#pragma unroll
            for (int i = 0; i < 2; i++)
                wmma::load_matrix_sync(af[i], (const __half*)sA + (wm*32 + i*16)*LDK + ks*16, LDK);
#pragma unroll
            for (int j = 0; j < 4; j++) {
                wmma::fragment<wmma::matrix_b, 16, 16, 16, __half, wmma::col_major> bf;
                wmma::load_matrix_sync(bf, (const __half*)sB + (wn*64 + j*16)*LDK + ks*16, LDK);
#pragma unroll
                for (int i = 0; i < 2; i++)
                    wmma::mma_sync(acc[i][j], af[i], bf, acc[i][j]);
            }
        }
    }

#pragma unroll
    for (int i = 0; i < 2; i++)
#pragma unroll
        for (int j = 0; j < 4; j++)
            wmma::store_matrix_sync(stage + (wm*32 + i*16)*132 + wn*64 + j*16,
                                    acc[i][j], 132, wmma::mem_row_major);
    __syncthreads();   // stage complete; all sA/sB reads done -> sH may be written

    float sc = fminf(fmaxf(rs[0], 0.0f), 1.5f);
    float4 gg, bb4;
    if (doNext) {
        gg  = *(const float4*)(lng + lane*4);
        bb4 = *(const float4*)(lnb + lane*4);
    }
#pragma unroll
    for (int rr = 0; rr < 16; rr++) {
        int row = warp*16 + rr;
        long m = m0 + row;
        float4 a4 = *(const float4*)&stage[row*132 + lane*4];
        float4 r4 = *(const float4*)(X + m*DD + lane*4);
        float4 v;
        v.x = r4.x + sc*a4.x; v.y = r4.y + sc*a4.y;
        v.z = r4.z + sc*a4.z; v.w = r4.w + sc*a4.w;
        *(float4*)(X + m*DD + lane*4) = v;
        if (doNext) {
            float s = v.x + v.y + v.z + v.w;
#pragma unroll
            for (int o = 16; o > 0; o >>= 1) s += __shfl_xor_sync(0xffffffffu, s, o);
            float mm = s * (1.0f/DD);
            float d0 = v.x-mm, d1 = v.y-mm, d2 = v.z-mm, d3 = v.w-mm;
            float q = d0*d0 + d1*d1 + d2*d2 + d3*d3;
#pragma unroll
            for (int o = 16; o > 0; o >>= 1) q += __shfl_xor_sync(0xffffffffu, q, o);
            float r = rsqrtf(q * (1.0f/DD) + 1e-5f);
            union { __half2 h[2]; uint2 u2; } pk;
            pk.h[0] = __floats2half2_rn(d0*r*gg.x + bb4.x, d1*r*gg.y + bb4.y);
            pk.h[1] = __floats2half2_rn(d2*r*gg.z + bb4.z, d3*r*gg.w + bb4.w);
            *(uint2*)(sH + row*(LDA1*2) + lane*8) = pk.u2;
        }
    }

    if (!doNext) return;

    // ---------------- phase 2: XZ_next = H @ Wi_next^T ----------------
    int pm = warp & 3, pn = warp >> 2;               // phase-2 warp tile 32 x 32

    for (int nb = 0; nb < 8; nb++) {
        long n0 = (long)nb * 64;
        __syncthreads();                              // sH ready (nb=0) / stage1 reads done
#pragma unroll
        for (int u = 0; u < 4; u++) {
            int id = t + u*256;                      // 1024 chunks
            int r = id >> 4, c = id & 15;
            *(uint4*)(sW + r*(LDA1*2) + c*16) =
                *(const uint4*)(Wi_next + (n0 + r)*(long)DD + c*8);
        }
        __syncthreads();

        wmma::fragment<wmma::accumulator, 16, 16, 16, float> acc2[2][2];
#pragma unroll
        for (int i = 0; i < 2; i++)
#pragma unroll
            for (int j = 0; j < 2; j++) wmma::fill_fragment(acc2[i][j], 0.0f);

#pragma unroll
        for (int ks = 0; ks < 8; ks++) {
            wmma::fragment<wmma::matrix_a, 16, 16, 16, __half, wmma::row_major> af[2];
            wmma::fragment<wmma::matrix_b, 16, 16, 16, __half, wmma::col_major> bf[2];
#pragma unroll
            for (int i = 0; i < 2; i++)
                wmma::load_matrix_sync(af[i], (const __half*)sH + (pm*32 + i*16)*LDA1 + ks*16, LDA1);
#pragma unroll
            for (int j = 0; j < 2; j++)
                wmma::load_matrix_sync(bf[j], (const __half*)sW + (pn*32 + j*16)*LDA1 + ks*16, LDA1);
#pragma unroll
            for (int i = 0; i < 2; i++)
#pragma unroll
                for (int j = 0; j < 2; j++)
                    wmma::mma_sync(acc2[i][j], af[i], bf[j], acc2[i][j]);
        }
#pragma unroll
        for (int i = 0; i < 2; i++)
#pragma unroll
            for (int j = 0; j < 2; j++)
                wmma::store_matrix_sync(stage1 + (pm*32 + i*16)*68 + pn*32 + j*16,
                                        acc2[i][j], 68, wmma::mem_row_major);
        __syncthreads();
#pragma unroll
        for (int u = 0; u < 8; u++) {
            int id = t + u*256;                      // 2048 groups of 4
            int r = id >> 4, q = id & 15;
            float4 v;
            v.x = stage1[r*68 + q*4 + 0]; v.y = stage1[r*68 + q*4 + 1];
            v.z = stage1[r*68 + q*4 + 2]; v.w = stage1[r*68 + q*4 + 3];
            union { __half2 h[2]; uint2 u2; } pk;
            pk.h[0] = __floats2half2_rn(v.x, v.y);
            pk.h[1] = __floats2half2_rn(v.z, v.w);
            *(uint2*)(XZ + (m0 + r)*(long)(2*DIi) + n0 + q*4) = pk.u2;
        }
    }
}

// ------------------ fused conv(k=4) + S4D recurrence + sigmoid gate ------------
__global__ void __launch_bounds__(256) s4d_kernel(const float* __restrict__ conv_w,
                                                  const float* __restrict__ conv_b,
                                                  const float* __restrict__ ssm_D,
                                                  int li) {
    __shared__ float sP [NNt*NSv];
    __shared__ float sCF[NNt*NSv];
    int c = threadIdx.x;
    int b = blockIdx.x;
    for (int i = c; i < NNt*NSv; i += 256) {
        sP [i] = g_P [li*NNt*NSv + i];
        sCF[i] = g_CF[li*NNt*NSv + i];
    }
    float w0 = conv_w[c*4+0], w1 = conv_w[c*4+1], w2 = conv_w[c*4+2], w3 = conv_w[c*4+3];
    float cb = conv_b[c];
    float Dp = ssm_D[0];
    __syncthreads();

    float S[NSv];
#pragma unroll
    for (int i = 0; i < NSv; i++) S[i] = 0.0f;
    float x0 = 0.f, x1 = 0.f, x2 = 0.f, x3 = 0.f;

    const __half* xzb = g_XZ + (long)b*NNt*(2*DIi);
    __half* yb = g_Y + (long)b*NNt*DIi;

#pragma unroll 2
    for (int l = 0; l < NNt; l++) {
        float xp = __half2float(xzb[l*(2*DIi) + c]);
        float zz = __half2float(xzb[l*(2*DIi) + DIi + c]);
        x0 = x1; x1 = x2; x2 = x3; x3 = xp;
        float xc = fmaf(w0, x0, fmaf(w1, x1, fmaf(w2, x2, fmaf(w3, x3, cb))));

        const float4* p4 = (const float4*)&sP [l*NSv];
        const float4* f4 = (const float4*)&sCF[l*NSv];
        float ys0 = Dp * xc, ys1 = 0.f, ys2 = 0.f, ys3 = 0.f;
#pragma unroll
        for (int q = 0; q < 4; q++) {
            float4 p = p4[q], f = f4[q];
            S[q*4+0] = fmaf(p.x, xc, S[q*4+0]); ys0 = fmaf(f.x, S[q*4+0], ys0);
            S[q*4+1] = fmaf(p.y, xc, S[q*4+1]); ys1 = fmaf(f.y, S[q*4+1], ys1);
            S[q*4+2] = fmaf(p.z, xc, S[q*4+2]); ys2 = fmaf(f.z, S[q*4+2], ys2);
            S[q*4+3] = fmaf(p.w, xc, S[q*4+3]); ys3 = fmaf(f.w, S[q*4+3], ys3);
        }
        float ys = (ys0 + ys1) + (ys2 + ys3);
        float e  = __expf(-zz);
        yb[l*DIi + c] = __float2half_rn(ys / (1.0f + e));
    }
}

// ------------------ final LN + normalize + importance MLP -> logits ------------
__global__ void __launch_bounds__(256) ftoken_kernel(const float* __restrict__ fin_g,
                                                     const float* __restrict__ fin_b,
                                                     const float* __restrict__ W1,
                                                     const float* __restrict__ b1,
                                                     const float* __restrict__ W2,
                                                     const float* __restrict__ b2,
                                                     float* __restrict__ out_tokens,
                                                     float* __restrict__ out_logits) {
    __shared__ float4 sW1[32*64];
    __shared__ float  sW2[64], sb1[64];
    __shared__ float  stn[8][132];
    int t = threadIdx.x;
    for (int f = t; f < 2048; f += 256) {
        int j = f >> 5, k4 = f & 31;
        sW1[k4*64 + j] = ((const float4*)W1)[f];
    }
    if (t < 64) { sW2[t] = W2[t]; sb1[t] = b1[t]; }
    __syncthreads();

    int lane = t & 31, w = t >> 5;
    long tk = (long)blockIdx.x * 8 + w;
    float4 v = *(const float4*)(g_X + tk*DD + lane*4);
    float s = v.x + v.y + v.z + v.w;
#pragma unroll
    for (int o = 16; o > 0; o >>= 1) s += __shfl_xor_sync(0xffffffffu, s, o);
    float m = s * (1.0f/DD);
    float d0 = v.x-m, d1 = v.y-m, d2 = v.z-m, d3 = v.w-m;
    float q = d0*d0 + d1*d1 + d2*d2 + d3*d3;
#pragma unroll
    for (int o = 16; o > 0; o >>= 1) q += __shfl_xor_sync(0xffffffffu, q, o);
    float r = rsqrtf(q * (1.0f/DD) + 1e-5f);
    float4 gg = *(const float4*)(fin_g + lane*4);
    float4 bb = *(const float4*)(fin_b + lane*4);
    float4 tok;
    tok.x = d0*r*gg.x + bb.x; tok.y = d1*r*gg.y + bb.y;
    tok.z = d2*r*gg.z + bb.z; tok.w = d3*r*gg.w + bb.w;
    *(float4*)(out_tokens + tk*DD + lane*4) = tok;

    float ss = tok.x*tok.x + tok.y*tok.y + tok.z*tok.z + tok.w*tok.w;
#pragma unroll
    for (int o = 16; o > 0; o >>= 1) ss += __shfl_xor_sync(0xffffffffu, ss, o);
    float rn = 1.0f / fmaxf(sqrtf(ss), 1e-6f);
    float4 tn4; tn4.x = tok.x*rn; tn4.y = tok.y*rn; tn4.z = tok.z*rn; tn4.w = tok.w*rn;
    *(float4*)&stn[w][lane*4] = tn4;
    __syncwarp();

    float h0 = sb1[lane], h1 = sb1[lane + 32];
#pragma unroll 8
    for (int k4 = 0; k4 < 32; k4++) {
        float4 tt = *(const float4*)&stn[w][k4*4];
        float4 wa = sW1[k4*64 + lane];
        float4 wb = sW1[k4*64 + lane + 32];
        h0 += tt.x*wa.x + tt.y*wa.y + tt.z*wa.z + tt.w*wa.w;
        h1 += tt.x*wb.x + tt.y*wb.y + tt.z*wb.z + tt.w*wb.w;
    }
    h0 = 0.5f*h0*(1.0f + erff(h0*0.70710678118654752f));
    h1 = 0.5f*h1*(1.0f + erff(h1*0.70710678118654752f));
    float gl = h0*sW2[lane] + h1*sW2[lane + 32];
#pragma unroll
    for (int o = 16; o > 0; o >>= 1) gl += __shfl_xor_sync(0xffffffffu, gl, o);
    if (lane == 0) out_logits[tk] = gl + b2[0];
}

// ------------------ softmax over N + weighted token pool -> feats --------------
__global__ void __launch_bounds__(256) fbatch_kernel(const float* __restrict__ logits,
                                                     const float* __restrict__ tokens,
                                                     float* __restrict__ out_w,
                                                     float* __restrict__ out_feats) {
    __shared__ float sw[NNt];
    __shared__ float red[8];
    int b = blockIdx.x, t = threadIdx.x, lane = t & 31, w = t >> 5;
    float lg = logits[(long)b*NNt + t];
    float mx = lg;
#pragma unroll
    for (int o = 16; o > 0; o >>= 1) mx = fmaxf(mx, __shfl_xor_sync(0xffffffffu, mx, o));
    if (lane == 0) red[w] = mx;
    __syncthreads();
    float bm = red[0];
#pragma unroll
    for (int i = 1; i < 8; i++) bm = fmaxf(bm, red[i]);
    float e = expf(lg - bm);
    float se = e;
#pragma unroll
    for (int o = 16; o > 0; o >>= 1) se += __shfl_xor_sync(0xffffffffu, se, o);
    __syncthreads();
    if (lane == 0) red[w] = se;
    __syncthreads();
    float tot = 0.f;
#pragma unroll
    for (int i = 0; i < 8; i++) tot += red[i];
    float wv = e / tot;
    out_w[(long)b*NNt + t] = wv;
    sw[t] = wv;
    __syncthreads();
    if (t < DD) {
        float acc = 0.f;
        for (int n = 0; n < NNt; n++)
            acc += sw[n] * tokens[((long)b*NNt + n)*DD + t];
        out_feats[b*DD + t] = acc;
    }
}

// ------------------ three linear heads -----------------------------------------
__global__ void __launch_bounds__(192) heads_kernel(const float* __restrict__ feats,
        const float* __restrict__ texW, const float* __restrict__ texb,
        const float* __restrict__ edgeW, const float* __restrict__ edgeb,
        const float* __restrict__ strW, const float* __restrict__ strb,
        float* __restrict__ o_tex, float* __restrict__ o_edge, float* __restrict__ o_str) {
    __shared__ float sf[DD];
    int b = blockIdx.x, t = threadIdx.x;
    if (t < DD) sf[t] = feats[b*DD + t];
    __syncthreads();
    int head = t / 64, j = t % 64;
    const float* W  = (head == 0) ? texW : (head == 1) ? edgeW : strW;
    const float* bi = (head == 0) ? texb : (head == 1) ? edgeb : strb;
    float acc = bi[j];
#pragma unroll 4
    for (int k = 0; k < DD; k++) acc += sf[k] * W[j*DD + k];
    float* o = (head == 0) ? o_tex : (head == 1) ? o_edge : o_str;
    o[b*64 + j] = acc;
}

// ------------------ launch ------------------------------------------------------
extern "C" void kernel_launch(void* const* d_in, const int* in_sizes, int n_in,
                              void* d_out, int out_size) {
    const float* tokens_in = (const float*)d_in[0];
    const float* pos       = (const float*)d_in[1];
    const float* ln_g      = (const float*)d_in[2];
    const float* ln_b      = (const float*)d_in[3];
    const float* W_in      = (const float*)d_in[4];
    const float* conv_w    = (const float*)d_in[5];
    const float* conv_b    = (const float*)d_in[6];
    const float* ssm_B     = (const float*)d_in[7];
    const float* ssm_C     = (const float*)d_in[8];
    const float* log_dt    = (const float*)d_in[9];
    const float* ssm_D     = (const float*)d_in[10];
    const float* W_out     = (const float*)d_in[11];
    const float* res_scale = (const float*)d_in[12];
    const float* fin_g     = (const float*)d_in[13];
    const float* fin_b     = (const float*)d_in[14];
    const float* W1        = (const float*)d_in[15];
    const float* b1        = (const float*)d_in[16];
    const float* W2        = (const float*)d_in[17];
    const float* b2        = (const float*)d_in[18];
    const float* texW      = (const float*)d_in[19];
    const float* texb      = (const float*)d_in[20];
    const float* edgeW     = (const float*)d_in[21];
    const float* edgeb     = (const float*)d_in[22];
    const float* strW      = (const float*)d_in[23];
    const float* strb      = (const float*)d_in[24];

    float *pX, *pLG;
    __half *pXZ, *pH, *pY, *pWi, *pWo;
    cudaGetSymbolAddress((void**)&pX,  g_X);
    cudaGetSymbolAddress((void**)&pXZ, g_XZ);
    cudaGetSymbolAddress((void**)&pLG, g_LG);
    cudaGetSymbolAddress((void**)&pH,  g_H);
    cudaGetSymbolAddress((void**)&pY,  g_Y);
    cudaGetSymbolAddress((void**)&pWi, g_Wi);
    cudaGetSymbolAddress((void**)&pWo, g_Wo);

    const int SMEM1 = G1_AB + G1_BB + 34816;   // 87040  -> 2 CTAs/SM
    const int SMEM2 = 2*G2_MB + 67584;         // 104448 -> 2 CTAs/SM
    cudaFuncSetAttribute(gemm_in_kernel,
                         cudaFuncAttributeMaxDynamicSharedMemorySize, SMEM1);
    cudaFuncSetAttribute(gemm_out_kernel,
                         cudaFuncAttributeMaxDynamicSharedMemorySize, SMEM2);

    float* out     = (float*)d_out;
    float* o_feats = out;
    float* o_tex   = o_feats + (long)BB*DD;
    float* o_edge  = o_tex   + (long)BB*64;
    float* o_str   = o_edge  + (long)BB*64;
    float* o_tok   = o_str   + (long)BB*64;
    float* o_w     = o_tok   + (long)BB*NNt*DD;

    const long M = (long)MT;

    prep_kernel<<<NLv, NNt>>>(ssm_B, ssm_C, log_dt);
    wconv_kernel<<<(NLv*2*DIi*DD + 255)/256, 256>>>(W_in,  pWi, NLv*2*DIi*DD);
    wconv_kernel<<<(NLv*DD*DIi   + 255)/256, 256>>>(W_out, pWo, NLv*DD*DIi);
    ln_kernel<<<(unsigned)(M/4), 128>>>(tokens_in, pos, ln_g, ln_b);
    // layer 0 in-projection (standalone)
    gemm_in_kernel<<<(unsigned)(M/128), 256, SMEM1>>>(pH, pWi, pXZ);
    for (int li = 0; li < NLv; li++) {
        s4d_kernel<<<BB, DIi>>>(conv_w + li*DIi*4, conv_b + li*DIi, ssm_D + li, li);
        int doNext = (li < NLv - 1) ? 1 : 0;
        gemm_out_kernel<<<(unsigned)(M/128), 256, SMEM2>>>(
            pY, pWo + (long)li*DD*DIi,
            pX, res_scale + li,
            ln_g + (li+1 < NLv ? (li+1)*DD : 0), ln_b + (li+1 < NLv ? (li+1)*DD : 0),
            pWi + (long)(li+1 < NLv ? (li+1) : 0)*2*DIi*DD, pXZ, doNext);
    }
    ftoken_kernel<<<(unsigned)(M/8), 256>>>(fin_g, fin_b, W1, b1, W2, b2, o_tok, pLG);
    fbatch_kernel<<<BB, NNt>>>(pLG, o_tok, o_w, o_feats);
    heads_kernel<<<BB, 192>>>(o_feats, texW, texb, edgeW, edgeb, strW, strb,
                              o_tex, o_edge, o_str);
}